// round 9
// baseline (speedup 1.0000x reference)
#include <cuda_runtime.h>

// Problem constants
#define TT    4096
#define EMB   1024
#define H2    512
#define G4    2048       // 4 * H2
#define NTAGS 5
#define START 3
#define STOP  4
#define NEGV  -10000.0f

// Recurrence: 64 CTAs per direction, 8 hidden units each, warp = hidden unit
#define NCTA   64
#define HPER   8
#define NREP   8         // h replication factor (poll-traffic spreading)
#define SENTB  0x7FC00000u

// -------------------- scratch (static device globals; no allocs) ------------
__device__ float d_G[2][TT * G4];               // input preactivations (64 MB)
__device__ float d_hrep[2][NREP][TT * H2];      // replicated hidden states (128 MB)
__device__ float d_feats[TT * 8];               // tag scores, stride 8

// -------------------- helpers ----------------------------------------------
__device__ __forceinline__ float4 ld_rlx_v4(const float* p) {
    float4 v;
    asm volatile("ld.relaxed.gpu.global.v4.f32 {%0,%1,%2,%3}, [%4];"
                 : "=f"(v.x), "=f"(v.y), "=f"(v.z), "=f"(v.w) : "l"(p) : "memory");
    return v;
}
__device__ __forceinline__ void st_rlx_f32(float* p, float v) {
    asm volatile("st.relaxed.gpu.global.f32 [%0], %1;" :: "l"(p), "f"(v) : "memory");
}
__device__ __forceinline__ float tanh_fast(float x) {
    float y;
    asm("tanh.approx.f32 %0, %1;" : "=f"(y) : "f"(x));
    return y;
}
__device__ __forceinline__ float sigmoid_fast(float x) {
    return fmaf(0.5f, tanh_fast(0.5f * x), 0.5f);
}

// -------------------- kernel: sentinel-init d_hrep ---------------------------
// 2*NREP*TT*H2 floats = 33,554,432 floats = 8,388,608 uint4
__global__ void k_init() {
    size_t i = (size_t)blockIdx.x * blockDim.x + threadIdx.x;
    uint4 s; s.x = SENTB; s.y = SENTB; s.z = SENTB; s.w = SENTB;
    ((uint4*)d_hrep)[i] = s;
}

// -------------------- kernel: input GEMM  G = embed[sent] @ Wih^T + bias ----
// C tile 128x128, K tile 16, 256 threads, 8x8 blocking, double-buffered smem,
// embedding gather fused into the A load. dir==1 reads tokens in reverse.
__global__ __launch_bounds__(256) void k_gemm(
    const int*   __restrict__ sent, const float* __restrict__ embed,
    const float* __restrict__ Wf, const float* __restrict__ Wb,
    const float* __restrict__ bihf, const float* __restrict__ bhhf,
    const float* __restrict__ bihb, const float* __restrict__ bhhb) {
    int dir = blockIdx.z;
    const float* W  = dir ? Wb   : Wf;
    const float* b1 = dir ? bihb : bihf;
    const float* b2 = dir ? bhhb : bhhf;
    float* Gp = d_G[dir];

    __shared__ float As[2][16 * 128];
    __shared__ float Bs[2][16 * 128];

    int tid = threadIdx.x;
    int m0 = blockIdx.y * 128;
    int n0 = blockIdx.x * 128;
    int ty = tid >> 4, tx = tid & 15;

    int lrow[2], lkq[2];
    const float* Arow[2];
    const float* Brow[2];
#pragma unroll
    for (int h = 0; h < 2; h++) {
        int f = tid + h * 256;
        lrow[h] = f >> 2; lkq[h] = f & 3;
        int srcRow = m0 + lrow[h];
        if (dir) srcRow = TT - 1 - srcRow;
        int token = sent[srcRow];
        Arow[h] = embed + (size_t)token * EMB;
        Brow[h] = W + (size_t)(n0 + lrow[h]) * EMB;
    }

    float acc[8][8];
#pragma unroll
    for (int i = 0; i < 8; i++)
#pragma unroll
        for (int j = 0; j < 8; j++) acc[i][j] = 0.0f;

#pragma unroll
    for (int h = 0; h < 2; h++) {
        float4 va = *(const float4*)(Arow[h] + lkq[h] * 4);
        float4 vb = *(const float4*)(Brow[h] + lkq[h] * 4);
        As[0][(lkq[h]*4+0)*128 + lrow[h]] = va.x;
        As[0][(lkq[h]*4+1)*128 + lrow[h]] = va.y;
        As[0][(lkq[h]*4+2)*128 + lrow[h]] = va.z;
        As[0][(lkq[h]*4+3)*128 + lrow[h]] = va.w;
        Bs[0][(lkq[h]*4+0)*128 + lrow[h]] = vb.x;
        Bs[0][(lkq[h]*4+1)*128 + lrow[h]] = vb.y;
        Bs[0][(lkq[h]*4+2)*128 + lrow[h]] = vb.z;
        Bs[0][(lkq[h]*4+3)*128 + lrow[h]] = vb.w;
    }
    __syncthreads();

    for (int kt = 0; kt < EMB / 16; kt++) {
        int p = kt & 1;
        float4 va[2], vb[2];
        if (kt < EMB / 16 - 1) {
            int k0 = (kt + 1) * 16;
#pragma unroll
            for (int h = 0; h < 2; h++) {
                va[h] = *(const float4*)(Arow[h] + k0 + lkq[h] * 4);
                vb[h] = *(const float4*)(Brow[h] + k0 + lkq[h] * 4);
            }
        }
#pragma unroll
        for (int k = 0; k < 16; k++) {
            float a[8], bb[8];
#pragma unroll
            for (int i = 0; i < 8; i++) a[i]  = As[p][k * 128 + ty * 8 + i];
#pragma unroll
            for (int j = 0; j < 8; j++) bb[j] = Bs[p][k * 128 + tx * 8 + j];
#pragma unroll
            for (int i = 0; i < 8; i++)
#pragma unroll
                for (int j = 0; j < 8; j++) acc[i][j] += a[i] * bb[j];
        }
        if (kt < EMB / 16 - 1) {
            int q = 1 - p;
            __syncthreads();
#pragma unroll
            for (int h = 0; h < 2; h++) {
                As[q][(lkq[h]*4+0)*128 + lrow[h]] = va[h].x;
                As[q][(lkq[h]*4+1)*128 + lrow[h]] = va[h].y;
                As[q][(lkq[h]*4+2)*128 + lrow[h]] = va[h].z;
                As[q][(lkq[h]*4+3)*128 + lrow[h]] = va[h].w;
                Bs[q][(lkq[h]*4+0)*128 + lrow[h]] = vb[h].x;
                Bs[q][(lkq[h]*4+1)*128 + lrow[h]] = vb[h].y;
                Bs[q][(lkq[h]*4+2)*128 + lrow[h]] = vb[h].z;
                Bs[q][(lkq[h]*4+3)*128 + lrow[h]] = vb[h].w;
            }
            __syncthreads();
        }
    }

    float bias[8];
#pragma unroll
    for (int j = 0; j < 8; j++) {
        int n = n0 + tx * 8 + j;
        bias[j] = b1[n] + b2[n];
    }
#pragma unroll
    for (int i = 0; i < 8; i++) {
        int m = m0 + ty * 8 + i;
#pragma unroll
        for (int j = 0; j < 8; j++) {
            int n = n0 + tx * 8 + j;
            Gp[(size_t)m * G4 + n] = acc[i][j] + bias[j];
        }
    }
}

// -------------------- kernel: persistent LSTM recurrence --------------------
// 128 CTAs (64/dir), 256 threads = 8 warps. Warp w owns hidden unit hbase+w
// (all 4 gate rows). NO smem, NO __syncthreads: each lane polls its own
// 16-float k-chunk of h(t-1) straight from a replica (NaN sentinel, detected
// by one sum + s!=s). Lanes start FMAs as soon as THEIR producers publish —
// arrival spread overlaps compute. Butterfly all-reduce -> redundant
// activation -> lanes 0-7 publish hj to the 8 replicas. Self-timed dataflow.
__global__ void __launch_bounds__(256, 1) k_recur(
    const float* __restrict__ Whh_f, const float* __restrict__ Whh_b,
    const float* __restrict__ h0, const float* __restrict__ c0) {
    int dir   = blockIdx.x >> 6;
    int slice = blockIdx.x & 63;
    int hbase = slice * HPER;
    const float* Whh = dir ? Whh_b : Whh_f;
    const float* Gd  = d_G[dir];
    float* hrep = d_hrep[dir][0];            // replica r at offset r*TT*H2
    int tid = threadIdx.x;
    int w = tid >> 5;            // warp -> hidden unit hbase+w
    int lane = tid & 31;         // k-chunk [16*lane, 16*lane+16)

    // per-warp replica assignment spreads poll traffic across all 8 replicas
    const float* hpoll = d_hrep[dir][(slice ^ w) & 7];

    // weights: w4[g][q] = Whh[(g*H2 + hbase + w)*H2 + 16*lane + 4q ..+4)
    float4 w4[4][4];
#pragma unroll
    for (int g = 0; g < 4; g++) {
        const float* Wr = Whh + (size_t)(g * H2 + hbase + w) * H2 + 16 * lane;
#pragma unroll
        for (int q = 0; q < 4; q++) w4[g][q] = *(const float4*)(Wr + 4 * q);
    }

    float cj = c0[dir * H2 + hbase + w];     // identical in all lanes

    // G(0) broadcast load
    float gv0, gv1, gv2, gv3;
    {
        const float* Gt = Gd + hbase + w;
        gv0 = Gt[0]; gv1 = Gt[H2]; gv2 = Gt[2 * H2]; gv3 = Gt[3 * H2];
    }

    // h(-1) chunk from h0
    float4 ha, hb, hc, hd;
    {
        const float* p = h0 + dir * H2 + lane * 16;
        ha = *(const float4*)(p);
        hb = *(const float4*)(p + 4);
        hc = *(const float4*)(p + 8);
        hd = *(const float4*)(p + 12);
    }

    for (int t = 0; t < TT; t++) {
        // GEMV partials on this lane's k-chunk
        float a0, a1, a2, a3;
        a0  = w4[0][0].x*ha.x + w4[0][0].y*ha.y + w4[0][0].z*ha.z + w4[0][0].w*ha.w;
        a1  = w4[1][0].x*ha.x + w4[1][0].y*ha.y + w4[1][0].z*ha.z + w4[1][0].w*ha.w;
        a2  = w4[2][0].x*ha.x + w4[2][0].y*ha.y + w4[2][0].z*ha.z + w4[2][0].w*ha.w;
        a3  = w4[3][0].x*ha.x + w4[3][0].y*ha.y + w4[3][0].z*ha.z + w4[3][0].w*ha.w;
        a0 += w4[0][1].x*hb.x + w4[0][1].y*hb.y + w4[0][1].z*hb.z + w4[0][1].w*hb.w;
        a1 += w4[1][1].x*hb.x + w4[1][1].y*hb.y + w4[1][1].z*hb.z + w4[1][1].w*hb.w;
        a2 += w4[2][1].x*hb.x + w4[2][1].y*hb.y + w4[2][1].z*hb.z + w4[2][1].w*hb.w;
        a3 += w4[3][1].x*hb.x + w4[3][1].y*hb.y + w4[3][1].z*hb.z + w4[3][1].w*hb.w;
        a0 += w4[0][2].x*hc.x + w4[0][2].y*hc.y + w4[0][2].z*hc.z + w4[0][2].w*hc.w;
        a1 += w4[1][2].x*hc.x + w4[1][2].y*hc.y + w4[1][2].z*hc.z + w4[1][2].w*hc.w;
        a2 += w4[2][2].x*hc.x + w4[2][2].y*hc.y + w4[2][2].z*hc.z + w4[2][2].w*hc.w;
        a3 += w4[3][2].x*hc.x + w4[3][2].y*hc.y + w4[3][2].z*hc.z + w4[3][2].w*hc.w;
        a0 += w4[0][3].x*hd.x + w4[0][3].y*hd.y + w4[0][3].z*hd.z + w4[0][3].w*hd.w;
        a1 += w4[1][3].x*hd.x + w4[1][3].y*hd.y + w4[1][3].z*hd.z + w4[1][3].w*hd.w;
        a2 += w4[2][3].x*hd.x + w4[2][3].y*hd.y + w4[2][3].z*hd.z + w4[2][3].w*hd.w;
        a3 += w4[3][3].x*hd.x + w4[3][3].y*hd.y + w4[3][3].z*hd.z + w4[3][3].w*hd.w;

        // butterfly all-reduce (gate sums land in every lane)
#pragma unroll
        for (int off = 16; off > 0; off >>= 1) {
            a0 += __shfl_xor_sync(0xffffffffu, a0, off);
            a1 += __shfl_xor_sync(0xffffffffu, a1, off);
            a2 += __shfl_xor_sync(0xffffffffu, a2, off);
            a3 += __shfl_xor_sync(0xffffffffu, a3, off);
        }

        // redundant activation in all lanes
        float gi = a0 + gv0, gf = a1 + gv1, gg = a2 + gv2, go = a3 + gv3;
        cj = sigmoid_fast(gf) * cj + sigmoid_fast(gi) * tanh_fast(gg);
        float hj = sigmoid_fast(go) * tanh_fast(cj);

        // publish: lanes 0-7 store hj to the 8 replicas
        if (lane < NREP)
            st_rlx_f32(hrep + (size_t)lane * (TT * H2) + (size_t)t * H2 + hbase + w, hj);

        if (t + 1 < TT) {
            // prefetch G(t+1) — broadcast, issued a full step ahead of use
            const float* Gn = Gd + (size_t)(t + 1) * G4 + hbase + w;
            gv0 = Gn[0]; gv1 = Gn[H2]; gv2 = Gn[2 * H2]; gv3 = Gn[3 * H2];

            // poll own k-chunk of h(t); NaN-sentinel detected via sum!=sum
            const float* p = hpoll + (size_t)t * H2 + lane * 16;
            float s;
            do {
                ha = ld_rlx_v4(p);
                hb = ld_rlx_v4(p + 4);
                hc = ld_rlx_v4(p + 8);
                hd = ld_rlx_v4(p + 12);
                s = ((ha.x + ha.y) + (ha.z + ha.w))
                  + ((hb.x + hb.y) + (hb.z + hb.w))
                  + ((hc.x + hc.y) + (hc.z + hc.w))
                  + ((hd.x + hd.y) + (hd.z + hd.w));
            } while (s != s);
        }
    }
}

// -------------------- kernel: output projection feats = [hf|hb] @ Wout^T ----
__global__ void k_feats(const float* __restrict__ Wout,
                        const float* __restrict__ bout) {
    int t = blockIdx.x;
    int n = threadIdx.x >> 5;              // 5 warps -> 5 tags
    int lane = threadIdx.x & 31;
    const float* hf = d_hrep[0][0] + (size_t)t * H2;
    const float* hb = d_hrep[1][0] + (size_t)(TT - 1 - t) * H2;
    float s = 0.0f;
    const float* Wn = Wout + (size_t)n * (2 * H2);
#pragma unroll 4
    for (int k = lane; k < H2; k += 32) s += Wn[k] * hf[k];
#pragma unroll 4
    for (int k = lane; k < H2; k += 32) s += Wn[H2 + k] * hb[k];
#pragma unroll
    for (int off = 16; off > 0; off >>= 1) s += __shfl_xor_sync(0xffffffffu, s, off);
    if (lane == 0) d_feats[t * 8 + n] = s + bout[n];
}

// -------------------- kernel: Viterbi + backtrace (single CTA) --------------
__global__ void k_viterbi(const float* __restrict__ trans,
                          float* __restrict__ out, int out_size) {
    extern __shared__ float smem[];
    float* sfeat = smem;                                    // TT*8 floats
    unsigned char* sbp = (unsigned char*)(smem + TT * 8);   // TT*8 bytes

    int tid = threadIdx.x;
    const float4* d4 = (const float4*)d_feats;
    float4* s4 = (float4*)sfeat;
    for (int i = tid; i < (TT * 8) / 4; i += blockDim.x) s4[i] = d4[i];
    __syncthreads();

    if (tid < 32) {
        int lane = tid;
        int n = lane < NTAGS ? lane : NTAGS - 1;
        float t00=trans[0], t01=trans[1], t02=trans[2], t03=trans[3], t04=trans[4];
        float t10=trans[5], t11=trans[6], t12=trans[7], t13=trans[8], t14=trans[9];
        float t20=trans[10],t21=trans[11],t22=trans[12],t23=trans[13],t24=trans[14];
        float t30=trans[15],t31=trans[16],t32=trans[17],t33=trans[18],t34=trans[19];
        float t40=trans[20],t41=trans[21],t42=trans[22],t43=trans[23],t44=trans[24];
        float trn0 = trans[n*5+0], trn1 = trans[n*5+1], trn2 = trans[n*5+2],
              trn3 = trans[n*5+3], trn4 = trans[n*5+4];

        float f0 = (0 == START) ? 0.0f : NEGV;
        float f1 = (1 == START) ? 0.0f : NEGV;
        float f2 = (2 == START) ? 0.0f : NEGV;
        float f3 = (3 == START) ? 0.0f : NEGV;
        float f4 = (4 == START) ? 0.0f : NEGV;

        for (int t = 0; t < TT; t++) {
            float4 ft = *(const float4*)(sfeat + t * 8);
            float ft4 = sfeat[t * 8 + 4];

            float b = f0 + trn0; int bp = 0; float v;
            v = f1 + trn1; if (v > b) { b = v; bp = 1; }
            v = f2 + trn2; if (v > b) { b = v; bp = 2; }
            v = f3 + trn3; if (v > b) { b = v; bp = 3; }
            v = f4 + trn4; if (v > b) { b = v; bp = 4; }
            if (lane < NTAGS) sbp[t * 8 + lane] = (unsigned char)bp;

            float m0 = fmaxf(fmaxf(fmaxf(f0+t00, f1+t01), fmaxf(f2+t02, f3+t03)), f4+t04);
            float m1 = fmaxf(fmaxf(fmaxf(f0+t10, f1+t11), fmaxf(f2+t12, f3+t13)), f4+t14);
            float m2 = fmaxf(fmaxf(fmaxf(f0+t20, f1+t21), fmaxf(f2+t22, f3+t23)), f4+t24);
            float m3 = fmaxf(fmaxf(fmaxf(f0+t30, f1+t31), fmaxf(f2+t32, f3+t33)), f4+t34);
            float m4 = fmaxf(fmaxf(fmaxf(f0+t40, f1+t41), fmaxf(f2+t42, f3+t43)), f4+t44);
            f0 = m0 + ft.x; f1 = m1 + ft.y; f2 = m2 + ft.z; f3 = m3 + ft.w; f4 = m4 + ft4;
        }

        if (lane == 0) {
            float fv[NTAGS] = {f0, f1, f2, f3, f4};
            float best = fv[0] + trans[STOP * NTAGS + 0];
            int bt = 0;
#pragma unroll
            for (int p = 1; p < NTAGS; p++) {
                float s = fv[p] + trans[STOP * NTAGS + p];
                if (s > best) { best = s; bt = p; }
            }
            if (out_size > 0) out[0] = best;
            int tag = bt;
            if (1 + (TT - 1) < out_size) out[1 + (TT - 1)] = (float)tag;
            for (int t = TT - 1; t >= 1; t--) {
                tag = sbp[t * 8 + tag];
                if (t < out_size) out[t] = (float)tag;
            }
        }
    }
}

// -------------------- launcher ----------------------------------------------
extern "C" void kernel_launch(void* const* d_in, const int* in_sizes, int n_in,
                              void* d_out, int out_size) {
    const int*   sent  = (const int*)d_in[0];
    const float* h0    = (const float*)d_in[1];
    const float* c0    = (const float*)d_in[2];
    const float* embed = (const float*)d_in[3];
    const float* Wih_f = (const float*)d_in[4];
    const float* Whh_f = (const float*)d_in[5];
    const float* bih_f = (const float*)d_in[6];
    const float* bhh_f = (const float*)d_in[7];
    const float* Wih_b = (const float*)d_in[8];
    const float* Whh_b = (const float*)d_in[9];
    const float* bih_b = (const float*)d_in[10];
    const float* bhh_b = (const float*)d_in[11];
    const float* Wout  = (const float*)d_in[12];
    const float* bout  = (const float*)d_in[13];
    const float* trans = (const float*)d_in[14];
    float* out = (float*)d_out;

    k_init<<<16384, 512>>>();
    dim3 gg(G4 / 128, TT / 128, 2);
    k_gemm<<<gg, 256>>>(sent, embed, Wih_f, Wih_b,
                        bih_f, bhh_f, bih_b, bhh_b);
    k_recur<<<2 * NCTA, 256>>>(Whh_f, Whh_b, h0, c0);
    k_feats<<<TT, 160>>>(Wout, bout);

    int vit_smem = TT * 8 * (int)sizeof(float) + TT * 8;   // 163840 B
    cudaFuncSetAttribute(k_viterbi, cudaFuncAttributeMaxDynamicSharedMemorySize,
                         vit_smem);
    k_viterbi<<<1, 128, vit_smem>>>(trans, out, out_size);
}

// round 10
// speedup vs baseline: 5.4905x; 5.4905x over previous
#include <cuda_runtime.h>

// Problem constants
#define TT    4096
#define EMB   1024
#define H2    512
#define G4    2048       // 4 * H2
#define NTAGS 5
#define START 3
#define STOP  4
#define NEGV  -10000.0f

// Recurrence: 32 CTAs per direction, 16 hidden units each, warp = hidden unit
#define NCTA   32
#define HPER   16
#define NREP   8         // h replication factor (poll-traffic spreading)
#define SENTB  0x7FC00000u

// -------------------- scratch (static device globals; no allocs) ------------
__device__ float d_G[2][TT * G4];               // input preactivations (64 MB)
__device__ float d_hrep[2][NREP][TT * H2];      // replicated hidden states (128 MB)
__device__ float d_feats[TT * 8];               // tag scores, stride 8

// -------------------- helpers ----------------------------------------------
__device__ __forceinline__ float4 ld_rlx_v4(const float* p) {
    float4 v;
    asm volatile("ld.relaxed.gpu.global.v4.f32 {%0,%1,%2,%3}, [%4];"
                 : "=f"(v.x), "=f"(v.y), "=f"(v.z), "=f"(v.w) : "l"(p) : "memory");
    return v;
}
__device__ __forceinline__ void st_rlx_f32(float* p, float v) {
    asm volatile("st.relaxed.gpu.global.f32 [%0], %1;" :: "l"(p), "f"(v) : "memory");
}
__device__ __forceinline__ float tanh_fast(float x) {
    float y;
    asm("tanh.approx.f32 %0, %1;" : "=f"(y) : "f"(x));
    return y;
}
__device__ __forceinline__ float sigmoid_fast(float x) {
    return fmaf(0.5f, tanh_fast(0.5f * x), 0.5f);
}

// -------------------- kernel: sentinel-init d_hrep ---------------------------
// 2*NREP*TT*H2 floats = 33,554,432 floats = 8,388,608 uint4
__global__ void k_init() {
    size_t i = (size_t)blockIdx.x * blockDim.x + threadIdx.x;
    uint4 s; s.x = SENTB; s.y = SENTB; s.z = SENTB; s.w = SENTB;
    ((uint4*)d_hrep)[i] = s;
}

// -------------------- kernel: input GEMM  G = embed[sent] @ Wih^T + bias ----
// C tile 128x128, K tile 16, 256 threads, 8x8 blocking, double-buffered smem,
// embedding gather fused into the A load. dir==1 reads tokens in reverse.
__global__ __launch_bounds__(256) void k_gemm(
    const int*   __restrict__ sent, const float* __restrict__ embed,
    const float* __restrict__ Wf, const float* __restrict__ Wb,
    const float* __restrict__ bihf, const float* __restrict__ bhhf,
    const float* __restrict__ bihb, const float* __restrict__ bhhb) {
    int dir = blockIdx.z;
    const float* W  = dir ? Wb   : Wf;
    const float* b1 = dir ? bihb : bihf;
    const float* b2 = dir ? bhhb : bhhf;
    float* Gp = d_G[dir];

    __shared__ float As[2][16 * 128];
    __shared__ float Bs[2][16 * 128];

    int tid = threadIdx.x;
    int m0 = blockIdx.y * 128;
    int n0 = blockIdx.x * 128;
    int ty = tid >> 4, tx = tid & 15;

    int lrow[2], lkq[2];
    const float* Arow[2];
    const float* Brow[2];
#pragma unroll
    for (int h = 0; h < 2; h++) {
        int f = tid + h * 256;
        lrow[h] = f >> 2; lkq[h] = f & 3;
        int srcRow = m0 + lrow[h];
        if (dir) srcRow = TT - 1 - srcRow;
        int token = sent[srcRow];
        Arow[h] = embed + (size_t)token * EMB;
        Brow[h] = W + (size_t)(n0 + lrow[h]) * EMB;
    }

    float acc[8][8];
#pragma unroll
    for (int i = 0; i < 8; i++)
#pragma unroll
        for (int j = 0; j < 8; j++) acc[i][j] = 0.0f;

#pragma unroll
    for (int h = 0; h < 2; h++) {
        float4 va = *(const float4*)(Arow[h] + lkq[h] * 4);
        float4 vb = *(const float4*)(Brow[h] + lkq[h] * 4);
        As[0][(lkq[h]*4+0)*128 + lrow[h]] = va.x;
        As[0][(lkq[h]*4+1)*128 + lrow[h]] = va.y;
        As[0][(lkq[h]*4+2)*128 + lrow[h]] = va.z;
        As[0][(lkq[h]*4+3)*128 + lrow[h]] = va.w;
        Bs[0][(lkq[h]*4+0)*128 + lrow[h]] = vb.x;
        Bs[0][(lkq[h]*4+1)*128 + lrow[h]] = vb.y;
        Bs[0][(lkq[h]*4+2)*128 + lrow[h]] = vb.z;
        Bs[0][(lkq[h]*4+3)*128 + lrow[h]] = vb.w;
    }
    __syncthreads();

    for (int kt = 0; kt < EMB / 16; kt++) {
        int p = kt & 1;
        float4 va[2], vb[2];
        if (kt < EMB / 16 - 1) {
            int k0 = (kt + 1) * 16;
#pragma unroll
            for (int h = 0; h < 2; h++) {
                va[h] = *(const float4*)(Arow[h] + k0 + lkq[h] * 4);
                vb[h] = *(const float4*)(Brow[h] + k0 + lkq[h] * 4);
            }
        }
#pragma unroll
        for (int k = 0; k < 16; k++) {
            float a[8], bb[8];
#pragma unroll
            for (int i = 0; i < 8; i++) a[i]  = As[p][k * 128 + ty * 8 + i];
#pragma unroll
            for (int j = 0; j < 8; j++) bb[j] = Bs[p][k * 128 + tx * 8 + j];
#pragma unroll
            for (int i = 0; i < 8; i++)
#pragma unroll
                for (int j = 0; j < 8; j++) acc[i][j] += a[i] * bb[j];
        }
        if (kt < EMB / 16 - 1) {
            int q = 1 - p;
            __syncthreads();
#pragma unroll
            for (int h = 0; h < 2; h++) {
                As[q][(lkq[h]*4+0)*128 + lrow[h]] = va[h].x;
                As[q][(lkq[h]*4+1)*128 + lrow[h]] = va[h].y;
                As[q][(lkq[h]*4+2)*128 + lrow[h]] = va[h].z;
                As[q][(lkq[h]*4+3)*128 + lrow[h]] = va[h].w;
                Bs[q][(lkq[h]*4+0)*128 + lrow[h]] = vb[h].x;
                Bs[q][(lkq[h]*4+1)*128 + lrow[h]] = vb[h].y;
                Bs[q][(lkq[h]*4+2)*128 + lrow[h]] = vb[h].z;
                Bs[q][(lkq[h]*4+3)*128 + lrow[h]] = vb[h].w;
            }
            __syncthreads();
        }
    }

    float bias[8];
#pragma unroll
    for (int j = 0; j < 8; j++) {
        int n = n0 + tx * 8 + j;
        bias[j] = b1[n] + b2[n];
    }
#pragma unroll
    for (int i = 0; i < 8; i++) {
        int m = m0 + ty * 8 + i;
#pragma unroll
        for (int j = 0; j < 8; j++) {
            int n = n0 + tx * 8 + j;
            Gp[(size_t)m * G4 + n] = acc[i][j] + bias[j];
        }
    }
}

// -------------------- kernel: persistent LSTM recurrence --------------------
// 64 CTAs (32/dir), 512 threads = 16 warps; warp w owns hidden unit hbase+w
// (all 4 gate rows; lane covers k-chunk [16*lane,16*lane+16), 64 w/lane).
// Staged sync (R7 structure): tid<128 poll their v4 group of h(t-1) from a
// replica (NaN sentinel), write smem; ONE __syncthreads per step paces all
// pollers. Butterfly all-reduce -> redundant activation -> lanes 0-7 publish
// hj to the 8 replicas; own slice pre-staged by each warp's lane 0.
__global__ void __launch_bounds__(512, 1) k_recur(
    const float* __restrict__ Whh_f, const float* __restrict__ Whh_b,
    const float* __restrict__ h0, const float* __restrict__ c0) {
    int dir   = blockIdx.x >> 5;
    int slice = blockIdx.x & 31;
    int hbase = slice * HPER;
    const float* Whh = dir ? Whh_b : Whh_f;
    const float* Gd  = d_G[dir];
    float* hrep = d_hrep[dir][0];            // replica r at offset r*TT*H2
    const float* hpoll = d_hrep[dir][slice & 7];

    int tid = threadIdx.x;
    int w = tid >> 5;            // warp -> hidden unit u = hbase + w
    int lane = tid & 31;         // k-chunk [16*lane, 16*lane+16)
    int u = hbase + w;

    // weights: w4[g][q] = Whh[(g*H2 + u)*H2 + 16*lane + 4q ..+4)
    float4 w4[4][4];
#pragma unroll
    for (int g = 0; g < 4; g++) {
        const float* Wr = Whh + (size_t)(g * H2 + u) * H2 + 16 * lane;
#pragma unroll
        for (int q = 0; q < 4; q++) w4[g][q] = *(const float4*)(Wr + 4 * q);
    }

    __shared__ __align__(16) float sh[2][H2];

    float cj = c0[dir * H2 + u];             // identical in all lanes

    // G(0) broadcast load
    float gv0, gv1, gv2, gv3;
    {
        const float* Gt = Gd + u;
        gv0 = Gt[0]; gv1 = Gt[H2]; gv2 = Gt[2 * H2]; gv3 = Gt[3 * H2];
    }

    // stage h(-1) = h0
    if (tid < 128)
        *(float4*)(sh[0] + tid * 4) = *(const float4*)(h0 + dir * H2 + tid * 4);
    __syncthreads();

    // own slice = v4 groups [slice*4, slice*4+4); those are pre-staged locally
    bool is_poller = (tid < 128) && ((tid >> 2) != slice);

    for (int t = 0; t < TT; t++) {
        // GEMV on sh[t&1]
        const float4* sh4 = (const float4*)(sh[t & 1]);
        float a0 = 0.f, a1 = 0.f, a2 = 0.f, a3 = 0.f;
#pragma unroll
        for (int q = 0; q < 4; q++) {
            float4 hv = sh4[4 * lane + q];
            a0 += w4[0][q].x*hv.x + w4[0][q].y*hv.y + w4[0][q].z*hv.z + w4[0][q].w*hv.w;
            a1 += w4[1][q].x*hv.x + w4[1][q].y*hv.y + w4[1][q].z*hv.z + w4[1][q].w*hv.w;
            a2 += w4[2][q].x*hv.x + w4[2][q].y*hv.y + w4[2][q].z*hv.z + w4[2][q].w*hv.w;
            a3 += w4[3][q].x*hv.x + w4[3][q].y*hv.y + w4[3][q].z*hv.z + w4[3][q].w*hv.w;
        }
        // butterfly all-reduce (gate sums land in every lane)
#pragma unroll
        for (int off = 16; off > 0; off >>= 1) {
            a0 += __shfl_xor_sync(0xffffffffu, a0, off);
            a1 += __shfl_xor_sync(0xffffffffu, a1, off);
            a2 += __shfl_xor_sync(0xffffffffu, a2, off);
            a3 += __shfl_xor_sync(0xffffffffu, a3, off);
        }

        // redundant activation in all lanes
        float gi = a0 + gv0, gf = a1 + gv1, gg = a2 + gv2, go = a3 + gv3;
        cj = sigmoid_fast(gf) * cj + sigmoid_fast(gi) * tanh_fast(gg);
        float hj = sigmoid_fast(go) * tanh_fast(cj);

        // publish: lanes 0-7 store hj to the 8 replicas
        if (lane < NREP)
            st_rlx_f32(hrep + (size_t)lane * (TT * H2) + (size_t)t * H2 + u, hj);
        // pre-stage own unit for next step's smem buffer
        if (lane == 0) sh[(t + 1) & 1][u] = hj;

        if (t + 1 < TT) {
            // prefetch G(t+1) — broadcast, issued a full step ahead of use
            const float* Gn = Gd + (size_t)(t + 1) * G4 + u;
            gv0 = Gn[0]; gv1 = Gn[H2]; gv2 = Gn[2 * H2]; gv3 = Gn[3 * H2];

            // staged poll: tid<128 fetch their v4 group of h(t); NaN sentinel
            if (is_poller) {
                const float* p = hpoll + (size_t)t * H2 + tid * 4;
                float4 v; float s;
                do {
                    v = ld_rlx_v4(p);
                    s = (v.x + v.y) + (v.z + v.w);
                } while (s != s);
                *(float4*)(sh[(t + 1) & 1] + tid * 4) = v;
            }
            __syncthreads();
        }
    }
}

// -------------------- kernel: output projection feats = [hf|hb] @ Wout^T ----
__global__ void k_feats(const float* __restrict__ Wout,
                        const float* __restrict__ bout) {
    int t = blockIdx.x;
    int n = threadIdx.x >> 5;              // 5 warps -> 5 tags
    int lane = threadIdx.x & 31;
    const float* hf = d_hrep[0][0] + (size_t)t * H2;
    const float* hb = d_hrep[1][0] + (size_t)(TT - 1 - t) * H2;
    float s = 0.0f;
    const float* Wn = Wout + (size_t)n * (2 * H2);
#pragma unroll 4
    for (int k = lane; k < H2; k += 32) s += Wn[k] * hf[k];
#pragma unroll 4
    for (int k = lane; k < H2; k += 32) s += Wn[H2 + k] * hb[k];
#pragma unroll
    for (int off = 16; off > 0; off >>= 1) s += __shfl_xor_sync(0xffffffffu, s, off);
    if (lane == 0) d_feats[t * 8 + n] = s + bout[n];
}

// -------------------- kernel: Viterbi + backtrace (single CTA) --------------
// Lanes 0-4 hold the full forward vector in registers, redundantly compute
// all 5 updates; feat loads software-pipelined one step ahead.
__global__ void k_viterbi(const float* __restrict__ trans,
                          float* __restrict__ out, int out_size) {
    extern __shared__ float smem[];
    float* sfeat = smem;                                    // TT*8 floats
    unsigned char* sbp = (unsigned char*)(smem + TT * 8);   // TT*8 bytes

    int tid = threadIdx.x;
    const float4* d4 = (const float4*)d_feats;
    float4* s4 = (float4*)sfeat;
    for (int i = tid; i < (TT * 8) / 4; i += blockDim.x) s4[i] = d4[i];
    __syncthreads();

    if (tid < 32) {
        int lane = tid;
        int n = lane < NTAGS ? lane : NTAGS - 1;
        float t00=trans[0], t01=trans[1], t02=trans[2], t03=trans[3], t04=trans[4];
        float t10=trans[5], t11=trans[6], t12=trans[7], t13=trans[8], t14=trans[9];
        float t20=trans[10],t21=trans[11],t22=trans[12],t23=trans[13],t24=trans[14];
        float t30=trans[15],t31=trans[16],t32=trans[17],t33=trans[18],t34=trans[19];
        float t40=trans[20],t41=trans[21],t42=trans[22],t43=trans[23],t44=trans[24];
        float trn0 = trans[n*5+0], trn1 = trans[n*5+1], trn2 = trans[n*5+2],
              trn3 = trans[n*5+3], trn4 = trans[n*5+4];

        float f0 = (0 == START) ? 0.0f : NEGV;
        float f1 = (1 == START) ? 0.0f : NEGV;
        float f2 = (2 == START) ? 0.0f : NEGV;
        float f3 = (3 == START) ? 0.0f : NEGV;
        float f4 = (4 == START) ? 0.0f : NEGV;

        float4 ft = *(const float4*)(sfeat);
        float ft4 = sfeat[4];

        for (int t = 0; t < TT; t++) {
            float4 ftn; float ftn4 = 0.0f;
            ftn.x = ftn.y = ftn.z = ftn.w = 0.0f;
            if (t + 1 < TT) {
                ftn = *(const float4*)(sfeat + (t + 1) * 8);
                ftn4 = sfeat[(t + 1) * 8 + 4];
            }

            float b = f0 + trn0; int bp = 0; float v;
            v = f1 + trn1; if (v > b) { b = v; bp = 1; }
            v = f2 + trn2; if (v > b) { b = v; bp = 2; }
            v = f3 + trn3; if (v > b) { b = v; bp = 3; }
            v = f4 + trn4; if (v > b) { b = v; bp = 4; }
            if (lane < NTAGS) sbp[t * 8 + lane] = (unsigned char)bp;

            float m0 = fmaxf(fmaxf(fmaxf(f0+t00, f1+t01), fmaxf(f2+t02, f3+t03)), f4+t04);
            float m1 = fmaxf(fmaxf(fmaxf(f0+t10, f1+t11), fmaxf(f2+t12, f3+t13)), f4+t14);
            float m2 = fmaxf(fmaxf(fmaxf(f0+t20, f1+t21), fmaxf(f2+t22, f3+t23)), f4+t24);
            float m3 = fmaxf(fmaxf(fmaxf(f0+t30, f1+t31), fmaxf(f2+t32, f3+t33)), f4+t34);
            float m4 = fmaxf(fmaxf(fmaxf(f0+t40, f1+t41), fmaxf(f2+t42, f3+t43)), f4+t44);
            f0 = m0 + ft.x; f1 = m1 + ft.y; f2 = m2 + ft.z; f3 = m3 + ft.w; f4 = m4 + ft4;

            ft = ftn; ft4 = ftn4;
        }

        if (lane == 0) {
            float fv[NTAGS] = {f0, f1, f2, f3, f4};
            float best = fv[0] + trans[STOP * NTAGS + 0];
            int bt = 0;
#pragma unroll
            for (int p = 1; p < NTAGS; p++) {
                float s = fv[p] + trans[STOP * NTAGS + p];
                if (s > best) { best = s; bt = p; }
            }
            if (out_size > 0) out[0] = best;
            int tag = bt;
            if (1 + (TT - 1) < out_size) out[1 + (TT - 1)] = (float)tag;
            for (int t = TT - 1; t >= 1; t--) {
                tag = sbp[t * 8 + tag];
                if (t < out_size) out[t] = (float)tag;
            }
        }
    }
}

// -------------------- launcher ----------------------------------------------
extern "C" void kernel_launch(void* const* d_in, const int* in_sizes, int n_in,
                              void* d_out, int out_size) {
    const int*   sent  = (const int*)d_in[0];
    const float* h0    = (const float*)d_in[1];
    const float* c0    = (const float*)d_in[2];
    const float* embed = (const float*)d_in[3];
    const float* Wih_f = (const float*)d_in[4];
    const float* Whh_f = (const float*)d_in[5];
    const float* bih_f = (const float*)d_in[6];
    const float* bhh_f = (const float*)d_in[7];
    const float* Wih_b = (const float*)d_in[8];
    const float* Whh_b = (const float*)d_in[9];
    const float* bih_b = (const float*)d_in[10];
    const float* bhh_b = (const float*)d_in[11];
    const float* Wout  = (const float*)d_in[12];
    const float* bout  = (const float*)d_in[13];
    const float* trans = (const float*)d_in[14];
    float* out = (float*)d_out;

    k_init<<<16384, 512>>>();
    dim3 gg(G4 / 128, TT / 128, 2);
    k_gemm<<<gg, 256>>>(sent, embed, Wih_f, Wih_b,
                        bih_f, bhh_f, bih_b, bhh_b);
    k_recur<<<2 * NCTA, 512>>>(Whh_f, Whh_b, h0, c0);
    k_feats<<<TT, 160>>>(Wout, bout);

    int vit_smem = TT * 8 * (int)sizeof(float) + TT * 8;   // 163840 B
    cudaFuncSetAttribute(k_viterbi, cudaFuncAttributeMaxDynamicSharedMemorySize,
                         vit_smem);
    k_viterbi<<<1, 128, vit_smem>>>(trans, out, out_size);
}

// round 11
// speedup vs baseline: 7.9377x; 1.4457x over previous
#include <cuda_runtime.h>

// Problem constants
#define TT    4096
#define EMB   1024
#define H2    512
#define G4    2048       // 4 * H2
#define NTAGS 5
#define START 3
#define STOP  4
#define NEGV  -10000.0f

// Recurrence: 64 CTAs per direction, 8 hidden units each (R7 structure)
#define NCTA   64
#define HPER   8
#define NREP   8         // sync replication factor (poll-traffic spreading)
#define SWIN   4         // sync ring depth (slot = t & 3); safety needs >= 2

// -------------------- scratch (static device globals; no allocs) ------------
__device__ float d_G[2][TT * G4];               // input preactivations (64 MB)
__device__ float d_h[2][TT * H2];               // hidden history for feats (16 MB)
__device__ unsigned d_sync[2][NREP][SWIN][H2 * 2];  // (h,tag) pairs — 256 KB, L2-hot
__device__ float d_feats[TT * 8];               // tag scores, stride 8

// -------------------- helpers ----------------------------------------------
__device__ __forceinline__ uint4 ld_rlx_v4u(const unsigned* p) {
    uint4 v;
    asm volatile("ld.relaxed.gpu.global.v4.u32 {%0,%1,%2,%3}, [%4];"
                 : "=r"(v.x), "=r"(v.y), "=r"(v.z), "=r"(v.w) : "l"(p) : "memory");
    return v;
}
__device__ __forceinline__ void st_rlx_pair(unsigned* p, unsigned hbits, unsigned tag) {
    unsigned long long v = ((unsigned long long)tag << 32) | (unsigned long long)hbits;
    asm volatile("st.relaxed.gpu.global.b64 [%0], %1;" :: "l"(p), "l"(v) : "memory");
}
__device__ __forceinline__ float tanh_fast(float x) {
    float y;
    asm("tanh.approx.f32 %0, %1;" : "=f"(y) : "f"(x));
    return y;
}
__device__ __forceinline__ float sigmoid_fast(float x) {
    return fmaf(0.5f, tanh_fast(0.5f * x), 0.5f);
}

// -------------------- kernel: init sync ring tags ----------------------------
// d_sync = 2*8*4*1024 uints = 65536 uints = 16384 uint4
__global__ void k_init() {
    int i = blockIdx.x * blockDim.x + threadIdx.x;
    uint4 s; s.x = 0xFFFFFFFFu; s.y = 0xFFFFFFFFu; s.z = 0xFFFFFFFFu; s.w = 0xFFFFFFFFu;
    if (i < 16384) ((uint4*)d_sync)[i] = s;
}

// -------------------- kernel: input GEMM  G = embed[sent] @ Wih^T + bias ----
// C tile 128x128, K tile 16, 256 threads, 8x8 blocking, double-buffered smem,
// embedding gather fused into the A load. dir==1 reads tokens in reverse.
__global__ __launch_bounds__(256) void k_gemm(
    const int*   __restrict__ sent, const float* __restrict__ embed,
    const float* __restrict__ Wf, const float* __restrict__ Wb,
    const float* __restrict__ bihf, const float* __restrict__ bhhf,
    const float* __restrict__ bihb, const float* __restrict__ bhhb) {
    int dir = blockIdx.z;
    const float* W  = dir ? Wb   : Wf;
    const float* b1 = dir ? bihb : bihf;
    const float* b2 = dir ? bhhb : bhhf;
    float* Gp = d_G[dir];

    __shared__ float As[2][16 * 128];
    __shared__ float Bs[2][16 * 128];

    int tid = threadIdx.x;
    int m0 = blockIdx.y * 128;
    int n0 = blockIdx.x * 128;
    int ty = tid >> 4, tx = tid & 15;

    int lrow[2], lkq[2];
    const float* Arow[2];
    const float* Brow[2];
#pragma unroll
    for (int h = 0; h < 2; h++) {
        int f = tid + h * 256;
        lrow[h] = f >> 2; lkq[h] = f & 3;
        int srcRow = m0 + lrow[h];
        if (dir) srcRow = TT - 1 - srcRow;
        int token = sent[srcRow];
        Arow[h] = embed + (size_t)token * EMB;
        Brow[h] = W + (size_t)(n0 + lrow[h]) * EMB;
    }

    float acc[8][8];
#pragma unroll
    for (int i = 0; i < 8; i++)
#pragma unroll
        for (int j = 0; j < 8; j++) acc[i][j] = 0.0f;

#pragma unroll
    for (int h = 0; h < 2; h++) {
        float4 va = *(const float4*)(Arow[h] + lkq[h] * 4);
        float4 vb = *(const float4*)(Brow[h] + lkq[h] * 4);
        As[0][(lkq[h]*4+0)*128 + lrow[h]] = va.x;
        As[0][(lkq[h]*4+1)*128 + lrow[h]] = va.y;
        As[0][(lkq[h]*4+2)*128 + lrow[h]] = va.z;
        As[0][(lkq[h]*4+3)*128 + lrow[h]] = va.w;
        Bs[0][(lkq[h]*4+0)*128 + lrow[h]] = vb.x;
        Bs[0][(lkq[h]*4+1)*128 + lrow[h]] = vb.y;
        Bs[0][(lkq[h]*4+2)*128 + lrow[h]] = vb.z;
        Bs[0][(lkq[h]*4+3)*128 + lrow[h]] = vb.w;
    }
    __syncthreads();

    for (int kt = 0; kt < EMB / 16; kt++) {
        int p = kt & 1;
        float4 va[2], vb[2];
        if (kt < EMB / 16 - 1) {
            int k0 = (kt + 1) * 16;
#pragma unroll
            for (int h = 0; h < 2; h++) {
                va[h] = *(const float4*)(Arow[h] + k0 + lkq[h] * 4);
                vb[h] = *(const float4*)(Brow[h] + k0 + lkq[h] * 4);
            }
        }
#pragma unroll
        for (int k = 0; k < 16; k++) {
            float a[8], bb[8];
#pragma unroll
            for (int i = 0; i < 8; i++) a[i]  = As[p][k * 128 + ty * 8 + i];
#pragma unroll
            for (int j = 0; j < 8; j++) bb[j] = Bs[p][k * 128 + tx * 8 + j];
#pragma unroll
            for (int i = 0; i < 8; i++)
#pragma unroll
                for (int j = 0; j < 8; j++) acc[i][j] += a[i] * bb[j];
        }
        if (kt < EMB / 16 - 1) {
            int q = 1 - p;
            __syncthreads();
#pragma unroll
            for (int h = 0; h < 2; h++) {
                As[q][(lkq[h]*4+0)*128 + lrow[h]] = va[h].x;
                As[q][(lkq[h]*4+1)*128 + lrow[h]] = va[h].y;
                As[q][(lkq[h]*4+2)*128 + lrow[h]] = va[h].z;
                As[q][(lkq[h]*4+3)*128 + lrow[h]] = va[h].w;
                Bs[q][(lkq[h]*4+0)*128 + lrow[h]] = vb[h].x;
                Bs[q][(lkq[h]*4+1)*128 + lrow[h]] = vb[h].y;
                Bs[q][(lkq[h]*4+2)*128 + lrow[h]] = vb[h].z;
                Bs[q][(lkq[h]*4+3)*128 + lrow[h]] = vb[h].w;
            }
            __syncthreads();
        }
    }

    float bias[8];
#pragma unroll
    for (int j = 0; j < 8; j++) {
        int n = n0 + tx * 8 + j;
        bias[j] = b1[n] + b2[n];
    }
#pragma unroll
    for (int i = 0; i < 8; i++) {
        int m = m0 + ty * 8 + i;
#pragma unroll
        for (int j = 0; j < 8; j++) {
            int n = n0 + tx * 8 + j;
            Gp[(size_t)m * G4 + n] = acc[i][j] + bias[j];
        }
    }
}

// -------------------- kernel: persistent LSTM recurrence --------------------
// 128 CTAs (64/dir), 256 threads = 8 warps; warp w owns hidden unit hbase+w.
// R7 structure: staged poll (tid<128) + ONE __syncthreads per step. Sync via a
// 256KB L2-resident ring of (h,tag) pairs: producer st.relaxed.b64 (atomic
// pair), consumer polls until tag == t. Slot = t&3; reuse is safe because a
// producer reaches step t+4 only after all CTAs consumed step t+2.
__global__ void __launch_bounds__(256, 1) k_recur(
    const float* __restrict__ Whh_f, const float* __restrict__ Whh_b,
    const float* __restrict__ h0, const float* __restrict__ c0) {
    int dir   = blockIdx.x >> 6;
    int slice = blockIdx.x & 63;
    int hbase = slice * HPER;
    const float* Whh = dir ? Whh_b : Whh_f;
    const float* Gd  = d_G[dir];
    float* hout = d_h[dir];

    int tid = threadIdx.x;
    int w = tid >> 5;            // warp -> hidden unit u = hbase + w
    int lane = tid & 31;         // k-chunk [16*lane, 16*lane+16)
    int u = hbase + w;
    int rep = slice & 7;         // which replica this CTA polls

    // weights: w4[g][q] = Whh[(g*H2 + u)*H2 + 16*lane + 4q ..+4)
    float4 w4[4][4];
#pragma unroll
    for (int g = 0; g < 4; g++) {
        const float* Wr = Whh + (size_t)(g * H2 + u) * H2 + 16 * lane;
#pragma unroll
        for (int q = 0; q < 4; q++) w4[g][q] = *(const float4*)(Wr + 4 * q);
    }

    __shared__ __align__(16) float sh[2][H2];

    float cj = c0[dir * H2 + u];             // identical in all lanes

    // G prefetch pipeline, depth 2 (G is a DRAM stream)
    float gc0, gc1, gc2, gc3;                // step t
    float gn0, gn1, gn2, gn3;                // step t+1
    {
        const float* Gt = Gd + u;
        gc0 = Gt[0]; gc1 = Gt[H2]; gc2 = Gt[2 * H2]; gc3 = Gt[3 * H2];
        const float* Gm = Gd + (size_t)G4 + u;
        gn0 = Gm[0]; gn1 = Gm[H2]; gn2 = Gm[2 * H2]; gn3 = Gm[3 * H2];
    }

    // stage h(-1) = h0 (no polling)
    if (tid < 128)
        *(float4*)(sh[0] + tid * 4) = *(const float4*)(h0 + dir * H2 + tid * 4);
    __syncthreads();

    // own slice = h elems [slice*8, slice*8+8) -> pollers tid/2 == slice skip
    bool is_poller = (tid < 128) && ((tid >> 1) != slice);

    for (int t = 0; t < TT; t++) {
        // GEMV on sh[t&1]
        const float4* sh4 = (const float4*)(sh[t & 1]);
        float a0 = 0.f, a1 = 0.f, a2 = 0.f, a3 = 0.f;
#pragma unroll
        for (int q = 0; q < 4; q++) {
            float4 hv = sh4[4 * lane + q];
            a0 += w4[0][q].x*hv.x + w4[0][q].y*hv.y + w4[0][q].z*hv.z + w4[0][q].w*hv.w;
            a1 += w4[1][q].x*hv.x + w4[1][q].y*hv.y + w4[1][q].z*hv.z + w4[1][q].w*hv.w;
            a2 += w4[2][q].x*hv.x + w4[2][q].y*hv.y + w4[2][q].z*hv.z + w4[2][q].w*hv.w;
            a3 += w4[3][q].x*hv.x + w4[3][q].y*hv.y + w4[3][q].z*hv.z + w4[3][q].w*hv.w;
        }

        // issue G(t+2) prefetch early (2 steps of cover for DRAM latency)
        float gf0 = 0.f, gf1 = 0.f, gf2 = 0.f, gf3 = 0.f;
        if (t + 2 < TT) {
            const float* Gf = Gd + (size_t)(t + 2) * G4 + u;
            gf0 = Gf[0]; gf1 = Gf[H2]; gf2 = Gf[2 * H2]; gf3 = Gf[3 * H2];
        }

        // butterfly all-reduce (gate sums land in every lane)
#pragma unroll
        for (int off = 16; off > 0; off >>= 1) {
            a0 += __shfl_xor_sync(0xffffffffu, a0, off);
            a1 += __shfl_xor_sync(0xffffffffu, a1, off);
            a2 += __shfl_xor_sync(0xffffffffu, a2, off);
            a3 += __shfl_xor_sync(0xffffffffu, a3, off);
        }

        // redundant activation in all lanes
        float gi = a0 + gc0, gf = a1 + gc1, gg = a2 + gc2, go = a3 + gc3;
        cj = sigmoid_fast(gf) * cj + sigmoid_fast(gi) * tanh_fast(gg);
        float hj = sigmoid_fast(go) * tanh_fast(cj);

        // publish (h, tag=t) atomically to the 8 replicas (lanes 0-7)
        if (lane < NREP)
            st_rlx_pair(&d_sync[dir][lane][t & (SWIN - 1)][u * 2],
                        __float_as_uint(hj), (unsigned)t);
        // history write for k_feats (lane 8), own-unit pre-stage (lane 0)
        if (lane == 8) hout[(size_t)t * H2 + u] = hj;
        if (lane == 0) sh[(t + 1) & 1][u] = hj;

        if (t + 1 < TT) {
            // staged poll: tid<128 fetch their 4 h elems of step t
            if (is_poller) {
                const unsigned* p = &d_sync[dir][rep][t & (SWIN - 1)][tid * 8];
                unsigned tt = (unsigned)t;
                uint4 va, vb;
                do {
                    va = ld_rlx_v4u(p);
                    vb = ld_rlx_v4u(p + 4);
                } while (va.y != tt || va.w != tt || vb.y != tt || vb.w != tt);
                float4 hv;
                hv.x = __uint_as_float(va.x); hv.y = __uint_as_float(va.z);
                hv.z = __uint_as_float(vb.x); hv.w = __uint_as_float(vb.z);
                *(float4*)(sh[(t + 1) & 1] + tid * 4) = hv;
            }
            __syncthreads();
        }
        gc0 = gn0; gc1 = gn1; gc2 = gn2; gc3 = gn3;
        gn0 = gf0; gn1 = gf1; gn2 = gf2; gn3 = gf3;
    }
}

// -------------------- kernel: output projection feats = [hf|hb] @ Wout^T ----
__global__ void k_feats(const float* __restrict__ Wout,
                        const float* __restrict__ bout) {
    int t = blockIdx.x;
    int n = threadIdx.x >> 5;              // 5 warps -> 5 tags
    int lane = threadIdx.x & 31;
    const float* hf = d_h[0] + (size_t)t * H2;
    const float* hb = d_h[1] + (size_t)(TT - 1 - t) * H2;
    float s = 0.0f;
    const float* Wn = Wout + (size_t)n * (2 * H2);
#pragma unroll 4
    for (int k = lane; k < H2; k += 32) s += Wn[k] * hf[k];
#pragma unroll 4
    for (int k = lane; k < H2; k += 32) s += Wn[H2 + k] * hb[k];
#pragma unroll
    for (int off = 16; off > 0; off >>= 1) s += __shfl_xor_sync(0xffffffffu, s, off);
    if (lane == 0) d_feats[t * 8 + n] = s + bout[n];
}

// -------------------- kernel: Viterbi + backtrace (single CTA) --------------
// Lanes 0-4 hold the full forward vector in registers, redundantly compute
// all 5 updates; feat loads software-pipelined one step ahead.
__global__ void k_viterbi(const float* __restrict__ trans,
                          float* __restrict__ out, int out_size) {
    extern __shared__ float smem[];
    float* sfeat = smem;                                    // TT*8 floats
    unsigned char* sbp = (unsigned char*)(smem + TT * 8);   // TT*8 bytes

    int tid = threadIdx.x;
    const float4* d4 = (const float4*)d_feats;
    float4* s4 = (float4*)sfeat;
    for (int i = tid; i < (TT * 8) / 4; i += blockDim.x) s4[i] = d4[i];
    __syncthreads();

    if (tid < 32) {
        int lane = tid;
        int n = lane < NTAGS ? lane : NTAGS - 1;
        float t00=trans[0], t01=trans[1], t02=trans[2], t03=trans[3], t04=trans[4];
        float t10=trans[5], t11=trans[6], t12=trans[7], t13=trans[8], t14=trans[9];
        float t20=trans[10],t21=trans[11],t22=trans[12],t23=trans[13],t24=trans[14];
        float t30=trans[15],t31=trans[16],t32=trans[17],t33=trans[18],t34=trans[19];
        float t40=trans[20],t41=trans[21],t42=trans[22],t43=trans[23],t44=trans[24];
        float trn0 = trans[n*5+0], trn1 = trans[n*5+1], trn2 = trans[n*5+2],
              trn3 = trans[n*5+3], trn4 = trans[n*5+4];

        float f0 = (0 == START) ? 0.0f : NEGV;
        float f1 = (1 == START) ? 0.0f : NEGV;
        float f2 = (2 == START) ? 0.0f : NEGV;
        float f3 = (3 == START) ? 0.0f : NEGV;
        float f4 = (4 == START) ? 0.0f : NEGV;

        float4 ft = *(const float4*)(sfeat);
        float ft4 = sfeat[4];

        for (int t = 0; t < TT; t++) {
            float4 ftn; float ftn4 = 0.0f;
            ftn.x = ftn.y = ftn.z = ftn.w = 0.0f;
            if (t + 1 < TT) {
                ftn = *(const float4*)(sfeat + (t + 1) * 8);
                ftn4 = sfeat[(t + 1) * 8 + 4];
            }

            float b = f0 + trn0; int bp = 0; float v;
            v = f1 + trn1; if (v > b) { b = v; bp = 1; }
            v = f2 + trn2; if (v > b) { b = v; bp = 2; }
            v = f3 + trn3; if (v > b) { b = v; bp = 3; }
            v = f4 + trn4; if (v > b) { b = v; bp = 4; }
            if (lane < NTAGS) sbp[t * 8 + lane] = (unsigned char)bp;

            float m0 = fmaxf(fmaxf(fmaxf(f0+t00, f1+t01), fmaxf(f2+t02, f3+t03)), f4+t04);
            float m1 = fmaxf(fmaxf(fmaxf(f0+t10, f1+t11), fmaxf(f2+t12, f3+t13)), f4+t14);
            float m2 = fmaxf(fmaxf(fmaxf(f0+t20, f1+t21), fmaxf(f2+t22, f3+t23)), f4+t24);
            float m3 = fmaxf(fmaxf(fmaxf(f0+t30, f1+t31), fmaxf(f2+t32, f3+t33)), f4+t34);
            float m4 = fmaxf(fmaxf(fmaxf(f0+t40, f1+t41), fmaxf(f2+t42, f3+t43)), f4+t44);
            f0 = m0 + ft.x; f1 = m1 + ft.y; f2 = m2 + ft.z; f3 = m3 + ft.w; f4 = m4 + ft4;

            ft = ftn; ft4 = ftn4;
        }

        if (lane == 0) {
            float fv[NTAGS] = {f0, f1, f2, f3, f4};
            float best = fv[0] + trans[STOP * NTAGS + 0];
            int bt = 0;
#pragma unroll
            for (int p = 1; p < NTAGS; p++) {
                float s = fv[p] + trans[STOP * NTAGS + p];
                if (s > best) { best = s; bt = p; }
            }
            if (out_size > 0) out[0] = best;
            int tag = bt;
            if (1 + (TT - 1) < out_size) out[1 + (TT - 1)] = (float)tag;
            for (int t = TT - 1; t >= 1; t--) {
                tag = sbp[t * 8 + tag];
                if (t < out_size) out[t] = (float)tag;
            }
        }
    }
}

// -------------------- launcher ----------------------------------------------
extern "C" void kernel_launch(void* const* d_in, const int* in_sizes, int n_in,
                              void* d_out, int out_size) {
    const int*   sent  = (const int*)d_in[0];
    const float* h0    = (const float*)d_in[1];
    const float* c0    = (const float*)d_in[2];
    const float* embed = (const float*)d_in[3];
    const float* Wih_f = (const float*)d_in[4];
    const float* Whh_f = (const float*)d_in[5];
    const float* bih_f = (const float*)d_in[6];
    const float* bhh_f = (const float*)d_in[7];
    const float* Wih_b = (const float*)d_in[8];
    const float* Whh_b = (const float*)d_in[9];
    const float* bih_b = (const float*)d_in[10];
    const float* bhh_b = (const float*)d_in[11];
    const float* Wout  = (const float*)d_in[12];
    const float* bout  = (const float*)d_in[13];
    const float* trans = (const float*)d_in[14];
    float* out = (float*)d_out;

    k_init<<<32, 512>>>();
    dim3 gg(G4 / 128, TT / 128, 2);
    k_gemm<<<gg, 256>>>(sent, embed, Wih_f, Wih_b,
                        bih_f, bhh_f, bih_b, bhh_b);
    k_recur<<<2 * NCTA, 256>>>(Whh_f, Whh_b, h0, c0);
    k_feats<<<TT, 160>>>(Wout, bout);

    int vit_smem = TT * 8 * (int)sizeof(float) + TT * 8;   // 163840 B
    cudaFuncSetAttribute(k_viterbi, cudaFuncAttributeMaxDynamicSharedMemorySize,
                         vit_smem);
    k_viterbi<<<1, 128, vit_smem>>>(trans, out, out_size);
}

// round 12
// speedup vs baseline: 8.8949x; 1.1206x over previous
#include <cuda_runtime.h>

// Problem constants
#define TT    4096
#define EMB   1024
#define H2    512
#define G4    2048       // 4 * H2
#define NTAGS 5
#define START 3
#define STOP  4
#define NEGV  -10000.0f

// Recurrence: 64 CTAs per direction, 8 hidden units each (R7/R11 structure)
#define NCTA   64
#define HPER   8
#define NREP   8         // sync replication factor (poll-traffic spreading)
#define SWIN   8         // sync ring depth (slot = t & 7)

typedef unsigned long long u64;

// -------------------- scratch (static device globals; no allocs) ------------
__device__ float d_G[2][TT * G4];               // input preactivations (64 MB)
__device__ float d_h[2][TT * H2];               // hidden history for feats (16 MB)
__device__ unsigned d_sync[2][NREP][SWIN][H2 * 2];  // (h,tag) pairs — 512 KB, L2-hot
__device__ float d_feats[TT * 8];               // tag scores, stride 8

// -------------------- helpers ----------------------------------------------
__device__ __forceinline__ uint4 ld_rlx_v4u(const unsigned* p) {
    uint4 v;
    asm volatile("ld.relaxed.gpu.global.v4.u32 {%0,%1,%2,%3}, [%4];"
                 : "=r"(v.x), "=r"(v.y), "=r"(v.z), "=r"(v.w) : "l"(p) : "memory");
    return v;
}
__device__ __forceinline__ void st_rlx_pair(unsigned* p, unsigned hbits, unsigned tag) {
    unsigned long long v = ((unsigned long long)tag << 32) | (unsigned long long)hbits;
    asm volatile("st.relaxed.gpu.global.b64 [%0], %1;" :: "l"(p), "l"(v) : "memory");
}
__device__ __forceinline__ float tanh_fast(float x) {
    float y;
    asm("tanh.approx.f32 %0, %1;" : "=f"(y) : "f"(x));
    return y;
}
__device__ __forceinline__ float sigmoid_fast(float x) {
    return fmaf(0.5f, tanh_fast(0.5f * x), 0.5f);
}
__device__ __forceinline__ u64 fma2(u64 a, u64 b, u64 c) {
    u64 d;
    asm("fma.rn.f32x2 %0, %1, %2, %3;" : "=l"(d) : "l"(a), "l"(b), "l"(c));
    return d;
}
__device__ __forceinline__ void unpack2(u64 v, float& lo, float& hi) {
    asm("mov.b64 {%0, %1}, %2;" : "=f"(lo), "=f"(hi) : "l"(v));
}

// -------------------- kernel: init sync ring tags ----------------------------
// d_sync = 2*8*8*1024 uints = 131072 uints = 32768 uint4
__global__ void k_init() {
    int i = blockIdx.x * blockDim.x + threadIdx.x;
    uint4 s; s.x = 0xFFFFFFFFu; s.y = 0xFFFFFFFFu; s.z = 0xFFFFFFFFu; s.w = 0xFFFFFFFFu;
    if (i < 32768) ((uint4*)d_sync)[i] = s;
}

// -------------------- kernel: input GEMM  G = embed[sent] @ Wih^T + bias ----
// C tile 128x128, K tile 16, 256 threads, 8x8 blocking, double-buffered smem,
// embedding gather fused into the A load. dir==1 reads tokens in reverse.
__global__ __launch_bounds__(256) void k_gemm(
    const int*   __restrict__ sent, const float* __restrict__ embed,
    const float* __restrict__ Wf, const float* __restrict__ Wb,
    const float* __restrict__ bihf, const float* __restrict__ bhhf,
    const float* __restrict__ bihb, const float* __restrict__ bhhb) {
    int dir = blockIdx.z;
    const float* W  = dir ? Wb   : Wf;
    const float* b1 = dir ? bihb : bihf;
    const float* b2 = dir ? bhhb : bhhf;
    float* Gp = d_G[dir];

    __shared__ float As[2][16 * 128];
    __shared__ float Bs[2][16 * 128];

    int tid = threadIdx.x;
    int m0 = blockIdx.y * 128;
    int n0 = blockIdx.x * 128;
    int ty = tid >> 4, tx = tid & 15;

    int lrow[2], lkq[2];
    const float* Arow[2];
    const float* Brow[2];
#pragma unroll
    for (int h = 0; h < 2; h++) {
        int f = tid + h * 256;
        lrow[h] = f >> 2; lkq[h] = f & 3;
        int srcRow = m0 + lrow[h];
        if (dir) srcRow = TT - 1 - srcRow;
        int token = sent[srcRow];
        Arow[h] = embed + (size_t)token * EMB;
        Brow[h] = W + (size_t)(n0 + lrow[h]) * EMB;
    }

    float acc[8][8];
#pragma unroll
    for (int i = 0; i < 8; i++)
#pragma unroll
        for (int j = 0; j < 8; j++) acc[i][j] = 0.0f;

#pragma unroll
    for (int h = 0; h < 2; h++) {
        float4 va = *(const float4*)(Arow[h] + lkq[h] * 4);
        float4 vb = *(const float4*)(Brow[h] + lkq[h] * 4);
        As[0][(lkq[h]*4+0)*128 + lrow[h]] = va.x;
        As[0][(lkq[h]*4+1)*128 + lrow[h]] = va.y;
        As[0][(lkq[h]*4+2)*128 + lrow[h]] = va.z;
        As[0][(lkq[h]*4+3)*128 + lrow[h]] = va.w;
        Bs[0][(lkq[h]*4+0)*128 + lrow[h]] = vb.x;
        Bs[0][(lkq[h]*4+1)*128 + lrow[h]] = vb.y;
        Bs[0][(lkq[h]*4+2)*128 + lrow[h]] = vb.z;
        Bs[0][(lkq[h]*4+3)*128 + lrow[h]] = vb.w;
    }
    __syncthreads();

    for (int kt = 0; kt < EMB / 16; kt++) {
        int p = kt & 1;
        float4 va[2], vb[2];
        if (kt < EMB / 16 - 1) {
            int k0 = (kt + 1) * 16;
#pragma unroll
            for (int h = 0; h < 2; h++) {
                va[h] = *(const float4*)(Arow[h] + k0 + lkq[h] * 4);
                vb[h] = *(const float4*)(Brow[h] + k0 + lkq[h] * 4);
            }
        }
#pragma unroll
        for (int k = 0; k < 16; k++) {
            float a[8], bb[8];
#pragma unroll
            for (int i = 0; i < 8; i++) a[i]  = As[p][k * 128 + ty * 8 + i];
#pragma unroll
            for (int j = 0; j < 8; j++) bb[j] = Bs[p][k * 128 + tx * 8 + j];
#pragma unroll
            for (int i = 0; i < 8; i++)
#pragma unroll
                for (int j = 0; j < 8; j++) acc[i][j] += a[i] * bb[j];
        }
        if (kt < EMB / 16 - 1) {
            int q = 1 - p;
            __syncthreads();
#pragma unroll
            for (int h = 0; h < 2; h++) {
                As[q][(lkq[h]*4+0)*128 + lrow[h]] = va[h].x;
                As[q][(lkq[h]*4+1)*128 + lrow[h]] = va[h].y;
                As[q][(lkq[h]*4+2)*128 + lrow[h]] = va[h].z;
                As[q][(lkq[h]*4+3)*128 + lrow[h]] = va[h].w;
                Bs[q][(lkq[h]*4+0)*128 + lrow[h]] = vb[h].x;
                Bs[q][(lkq[h]*4+1)*128 + lrow[h]] = vb[h].y;
                Bs[q][(lkq[h]*4+2)*128 + lrow[h]] = vb[h].z;
                Bs[q][(lkq[h]*4+3)*128 + lrow[h]] = vb[h].w;
            }
            __syncthreads();
        }
    }

    float bias[8];
#pragma unroll
    for (int j = 0; j < 8; j++) {
        int n = n0 + tx * 8 + j;
        bias[j] = b1[n] + b2[n];
    }
#pragma unroll
    for (int i = 0; i < 8; i++) {
        int m = m0 + ty * 8 + i;
#pragma unroll
        for (int j = 0; j < 8; j++) {
            int n = n0 + tx * 8 + j;
            Gp[(size_t)m * G4 + n] = acc[i][j] + bias[j];
        }
    }
}

// -------------------- kernel: persistent LSTM recurrence --------------------
// 128 CTAs (64/dir), 256 threads = 8 warps; warp w owns hidden unit hbase+w.
// R11 structure: staged poll (tid<128) + ONE __syncthreads per step; sync via
// L2-resident (h,tag) ring. GEMV in f32x2 (32 FFMA2/lane instead of 64 FFMA).
__global__ void __launch_bounds__(256, 1) k_recur(
    const float* __restrict__ Whh_f, const float* __restrict__ Whh_b,
    const float* __restrict__ h0, const float* __restrict__ c0) {
    int dir   = blockIdx.x >> 6;
    int slice = blockIdx.x & 63;
    int hbase = slice * HPER;
    const float* Whh = dir ? Whh_b : Whh_f;
    const float* Gd  = d_G[dir];
    float* hout = d_h[dir];

    int tid = threadIdx.x;
    int w = tid >> 5;            // warp -> hidden unit u = hbase + w
    int lane = tid & 31;
    int u = hbase + w;
    int rep = slice & 7;         // which replica this CTA polls

    // weights as f32x2 pairs: pair q of gate g = Whh[row*H2 + q*64 + lane*2 ..+1]
    u64 w2[4][8];
#pragma unroll
    for (int g = 0; g < 4; g++) {
        const u64* Wr = (const u64*)(Whh + (size_t)(g * H2 + u) * H2);
#pragma unroll
        for (int q = 0; q < 8; q++) w2[g][q] = Wr[q * 32 + lane];
    }

    __shared__ __align__(16) float sh[2][H2];

    float cj = c0[dir * H2 + u];             // identical in all lanes

    // G prefetch pipeline, depth 2 (G is a DRAM stream)
    float gc0, gc1, gc2, gc3;                // step t
    float gn0, gn1, gn2, gn3;                // step t+1
    {
        const float* Gt = Gd + u;
        gc0 = Gt[0]; gc1 = Gt[H2]; gc2 = Gt[2 * H2]; gc3 = Gt[3 * H2];
        const float* Gm = Gd + (size_t)G4 + u;
        gn0 = Gm[0]; gn1 = Gm[H2]; gn2 = Gm[2 * H2]; gn3 = Gm[3 * H2];
    }

    // stage h(-1) = h0 (no polling)
    if (tid < 128)
        *(float4*)(sh[0] + tid * 4) = *(const float4*)(h0 + dir * H2 + tid * 4);
    __syncthreads();

    // own slice = h elems [slice*8, slice*8+8) -> pollers tid/2 == slice skip
    bool is_poller = (tid < 128) && ((tid >> 1) != slice);

    for (int t = 0; t < TT; t++) {
        // GEMV on sh[t&1], f32x2: 32 FFMA2 per lane
        const u64* sh2 = (const u64*)(sh[t & 1]);
        u64 p0 = 0ull, p1 = 0ull, p2 = 0ull, p3 = 0ull;
#pragma unroll
        for (int q = 0; q < 8; q++) {
            u64 hv = sh2[q * 32 + lane];
            p0 = fma2(w2[0][q], hv, p0);
            p1 = fma2(w2[1][q], hv, p1);
            p2 = fma2(w2[2][q], hv, p2);
            p3 = fma2(w2[3][q], hv, p3);
        }
        float lo, hi;
        unpack2(p0, lo, hi); float a0 = lo + hi;
        unpack2(p1, lo, hi); float a1 = lo + hi;
        unpack2(p2, lo, hi); float a2 = lo + hi;
        unpack2(p3, lo, hi); float a3 = lo + hi;

        // issue G(t+2) prefetch early (2 steps of cover for DRAM latency)
        float gf0 = 0.f, gf1 = 0.f, gf2 = 0.f, gf3 = 0.f;
        if (t + 2 < TT) {
            const float* Gf = Gd + (size_t)(t + 2) * G4 + u;
            gf0 = Gf[0]; gf1 = Gf[H2]; gf2 = Gf[2 * H2]; gf3 = Gf[3 * H2];
        }

        // butterfly all-reduce (gate sums land in every lane)
#pragma unroll
        for (int off = 16; off > 0; off >>= 1) {
            a0 += __shfl_xor_sync(0xffffffffu, a0, off);
            a1 += __shfl_xor_sync(0xffffffffu, a1, off);
            a2 += __shfl_xor_sync(0xffffffffu, a2, off);
            a3 += __shfl_xor_sync(0xffffffffu, a3, off);
        }

        // redundant activation in all lanes
        float gi = a0 + gc0, gf = a1 + gc1, gg = a2 + gc2, go = a3 + gc3;
        cj = sigmoid_fast(gf) * cj + sigmoid_fast(gi) * tanh_fast(gg);
        float hj = sigmoid_fast(go) * tanh_fast(cj);

        // publish (h, tag=t) atomically to the 8 replicas (lanes 0-7)
        if (lane < NREP)
            st_rlx_pair(&d_sync[dir][lane][t & (SWIN - 1)][u * 2],
                        __float_as_uint(hj), (unsigned)t);
        // history write for k_feats (lane 8), own-unit pre-stage (lane 0)
        if (lane == 8) hout[(size_t)t * H2 + u] = hj;
        if (lane == 0) sh[(t + 1) & 1][u] = hj;

        if (t + 1 < TT) {
            // staged poll: tid<128 fetch their 4 h elems of step t
            if (is_poller) {
                const unsigned* p = &d_sync[dir][rep][t & (SWIN - 1)][tid * 8];
                unsigned tt = (unsigned)t;
                uint4 va, vb;
                do {
                    va = ld_rlx_v4u(p);
                    vb = ld_rlx_v4u(p + 4);
                } while (va.y != tt || va.w != tt || vb.y != tt || vb.w != tt);
                float4 hv;
                hv.x = __uint_as_float(va.x); hv.y = __uint_as_float(va.z);
                hv.z = __uint_as_float(vb.x); hv.w = __uint_as_float(vb.z);
                *(float4*)(sh[(t + 1) & 1] + tid * 4) = hv;
            }
            __syncthreads();
        }
        gc0 = gn0; gc1 = gn1; gc2 = gn2; gc3 = gn3;
        gn0 = gf0; gn1 = gf1; gn2 = gf2; gn3 = gf3;
    }
}

// -------------------- kernel: output projection feats = [hf|hb] @ Wout^T ----
__global__ void k_feats(const float* __restrict__ Wout,
                        const float* __restrict__ bout) {
    int t = blockIdx.x;
    int n = threadIdx.x >> 5;              // 5 warps -> 5 tags
    int lane = threadIdx.x & 31;
    const float* hf = d_h[0] + (size_t)t * H2;
    const float* hb = d_h[1] + (size_t)(TT - 1 - t) * H2;
    float s = 0.0f;
    const float* Wn = Wout + (size_t)n * (2 * H2);
#pragma unroll 4
    for (int k = lane; k < H2; k += 32) s += Wn[k] * hf[k];
#pragma unroll 4
    for (int k = lane; k < H2; k += 32) s += Wn[H2 + k] * hb[k];
#pragma unroll
    for (int off = 16; off > 0; off >>= 1) s += __shfl_xor_sync(0xffffffffu, s, off);
    if (lane == 0) d_feats[t * 8 + n] = s + bout[n];
}

// -------------------- kernel: Viterbi + backtrace (single CTA) --------------
// Lanes 0-4 hold the full forward vector in registers, redundantly compute
// all 5 updates; feat loads software-pipelined one step ahead.
__global__ void k_viterbi(const float* __restrict__ trans,
                          float* __restrict__ out, int out_size) {
    extern __shared__ float smem[];
    float* sfeat = smem;                                    // TT*8 floats
    unsigned char* sbp = (unsigned char*)(smem + TT * 8);   // TT*8 bytes

    int tid = threadIdx.x;
    const float4* d4 = (const float4*)d_feats;
    float4* s4 = (float4*)sfeat;
    for (int i = tid; i < (TT * 8) / 4; i += blockDim.x) s4[i] = d4[i];
    __syncthreads();

    if (tid < 32) {
        int lane = tid;
        int n = lane < NTAGS ? lane : NTAGS - 1;
        float t00=trans[0], t01=trans[1], t02=trans[2], t03=trans[3], t04=trans[4];
        float t10=trans[5], t11=trans[6], t12=trans[7], t13=trans[8], t14=trans[9];
        float t20=trans[10],t21=trans[11],t22=trans[12],t23=trans[13],t24=trans[14];
        float t30=trans[15],t31=trans[16],t32=trans[17],t33=trans[18],t34=trans[19];
        float t40=trans[20],t41=trans[21],t42=trans[22],t43=trans[23],t44=trans[24];
        float trn0 = trans[n*5+0], trn1 = trans[n*5+1], trn2 = trans[n*5+2],
              trn3 = trans[n*5+3], trn4 = trans[n*5+4];

        float f0 = (0 == START) ? 0.0f : NEGV;
        float f1 = (1 == START) ? 0.0f : NEGV;
        float f2 = (2 == START) ? 0.0f : NEGV;
        float f3 = (3 == START) ? 0.0f : NEGV;
        float f4 = (4 == START) ? 0.0f : NEGV;

        float4 ft = *(const float4*)(sfeat);
        float ft4 = sfeat[4];

        for (int t = 0; t < TT; t++) {
            float4 ftn; float ftn4 = 0.0f;
            ftn.x = ftn.y = ftn.z = ftn.w = 0.0f;
            if (t + 1 < TT) {
                ftn = *(const float4*)(sfeat + (t + 1) * 8);
                ftn4 = sfeat[(t + 1) * 8 + 4];
            }

            float b = f0 + trn0; int bp = 0; float v;
            v = f1 + trn1; if (v > b) { b = v; bp = 1; }
            v = f2 + trn2; if (v > b) { b = v; bp = 2; }
            v = f3 + trn3; if (v > b) { b = v; bp = 3; }
            v = f4 + trn4; if (v > b) { b = v; bp = 4; }
            if (lane < NTAGS) sbp[t * 8 + lane] = (unsigned char)bp;

            float m0 = fmaxf(fmaxf(fmaxf(f0+t00, f1+t01), fmaxf(f2+t02, f3+t03)), f4+t04);
            float m1 = fmaxf(fmaxf(fmaxf(f0+t10, f1+t11), fmaxf(f2+t12, f3+t13)), f4+t14);
            float m2 = fmaxf(fmaxf(fmaxf(f0+t20, f1+t21), fmaxf(f2+t22, f3+t23)), f4+t24);
            float m3 = fmaxf(fmaxf(fmaxf(f0+t30, f1+t31), fmaxf(f2+t32, f3+t33)), f4+t34);
            float m4 = fmaxf(fmaxf(fmaxf(f0+t40, f1+t41), fmaxf(f2+t42, f3+t43)), f4+t44);
            f0 = m0 + ft.x; f1 = m1 + ft.y; f2 = m2 + ft.z; f3 = m3 + ft.w; f4 = m4 + ft4;

            ft = ftn; ft4 = ftn4;
        }

        if (lane == 0) {
            float fv[NTAGS] = {f0, f1, f2, f3, f4};
            float best = fv[0] + trans[STOP * NTAGS + 0];
            int bt = 0;
#pragma unroll
            for (int p = 1; p < NTAGS; p++) {
                float s = fv[p] + trans[STOP * NTAGS + p];
                if (s > best) { best = s; bt = p; }
            }
            if (out_size > 0) out[0] = best;
            int tag = bt;
            if (1 + (TT - 1) < out_size) out[1 + (TT - 1)] = (float)tag;
            for (int t = TT - 1; t >= 1; t--) {
                tag = sbp[t * 8 + tag];
                if (t < out_size) out[t] = (float)tag;
            }
        }
    }
}

// -------------------- launcher ----------------------------------------------
extern "C" void kernel_launch(void* const* d_in, const int* in_sizes, int n_in,
                              void* d_out, int out_size) {
    const int*   sent  = (const int*)d_in[0];
    const float* h0    = (const float*)d_in[1];
    const float* c0    = (const float*)d_in[2];
    const float* embed = (const float*)d_in[3];
    const float* Wih_f = (const float*)d_in[4];
    const float* Whh_f = (const float*)d_in[5];
    const float* bih_f = (const float*)d_in[6];
    const float* bhh_f = (const float*)d_in[7];
    const float* Wih_b = (const float*)d_in[8];
    const float* Whh_b = (const float*)d_in[9];
    const float* bih_b = (const float*)d_in[10];
    const float* bhh_b = (const float*)d_in[11];
    const float* Wout  = (const float*)d_in[12];
    const float* bout  = (const float*)d_in[13];
    const float* trans = (const float*)d_in[14];
    float* out = (float*)d_out;

    k_init<<<64, 512>>>();
    dim3 gg(G4 / 128, TT / 128, 2);
    k_gemm<<<gg, 256>>>(sent, embed, Wih_f, Wih_b,
                        bih_f, bhh_f, bih_b, bhh_b);
    k_recur<<<2 * NCTA, 256>>>(Whh_f, Whh_b, h0, c0);
    k_feats<<<TT, 160>>>(Wout, bout);

    int vit_smem = TT * 8 * (int)sizeof(float) + TT * 8;   // 163840 B
    cudaFuncSetAttribute(k_viterbi, cudaFuncAttributeMaxDynamicSharedMemorySize,
                         vit_smem);
    k_viterbi<<<1, 128, vit_smem>>>(trans, out, out_size);
}